// round 1
// baseline (speedup 1.0000x reference)
#include <cuda_runtime.h>
#include <cuda_bf16.h>
#include <math.h>

// Problem constants (fixed shapes from setup_inputs)
constexpr int S  = 20;    // alphabet
constexpr int MM = 2;     // m
constexpr int KK = 2;     // k
constexpr int NB = 512;   // b
constexpr int LL = 512;   // L
constexpr int NRATES = 512;
constexpr int NT = 20;    // Taylor terms (n = 0..19), uniformization

// Scratch (no allocations allowed): coefficients, mu, and staged P matrices.
__device__ float  g_C[MM * KK * NT * S * S];     // C_n = M^n / n! per (m,k)
__device__ float  g_mu[MM * KK];
__device__ float4 g_P4[(MM * NB * KK * S * S) / 4];  // P staged as (m,b,k,S,S)

__device__ __forceinline__ float softplusf(float x) {
    // jax.nn.softplus(x) = logaddexp(x, 0) = max(x,0) + log1p(exp(-|x|))
    return fmaxf(x, 0.0f) + log1pf(expf(-fabsf(x)));
}

// ---------------------------------------------------------------------------
// Kernel A: per (m,k) build R, p, normalized Q, mu, and coefficient matrices
// C_n = M^n / n! with M = Qnorm + mu*I  (elementwise >= 0: uniformization).
// 4 blocks x 400 threads; work is tiny.
// ---------------------------------------------------------------------------
__global__ void setup_kernel(const float* __restrict__ exch,
                             const float* __restrict__ equi) {
    __shared__ float Qsh[S * S], Msh[S * S], Ca[S * S], Cb[S * S];
    __shared__ float psh[S], dsh[S];
    __shared__ float s_inv_mue, s_mu;

    const int mk  = blockIdx.x;          // 0..3
    const int tid = threadIdx.x;         // 0..399
    const int i = tid / S, j = tid % S;

    const float* E = exch + mk * S * S;

    // R = softplus(0.5*(E+E^T)), zero diagonal; then Q_off = R * p_j
    float r = (i == j) ? 0.0f : softplusf(0.5f * (E[i * S + j] + E[j * S + i]));

    if (tid == 0) {
        const float* q = equi + mk * S;
        float mx = -1e30f;
        for (int t = 0; t < S; t++) mx = fmaxf(mx, q[t]);
        float sm = 0.0f;
        for (int t = 0; t < S; t++) { float e = expf(q[t] - mx); psh[t] = e; sm += e; }
        float inv = 1.0f / sm;
        for (int t = 0; t < S; t++) psh[t] *= inv;
    }
    __syncthreads();

    float qv = r * psh[j];               // off-diagonal Q (diag 0)
    Qsh[tid] = qv;
    __syncthreads();

    if (j == 0) {                        // row sums d_i
        float d = 0.0f;
        for (int t = 0; t < S; t++) d += Qsh[i * S + t];
        dsh[i] = d;
    }
    __syncthreads();

    if (tid == 0) {
        float mue = 0.0f;
        for (int t = 0; t < S; t++) mue += psh[t] * dsh[t];
        mue = fmaxf(mue, 1e-16f);
        float inv = 1.0f / mue;
        float mu = 0.0f;
        for (int t = 0; t < S; t++) mu = fmaxf(mu, dsh[t] * inv);
        s_inv_mue = inv;
        s_mu = mu;
        g_mu[mk] = mu;
    }
    __syncthreads();

    const float inv = s_inv_mue, mu = s_mu;
    // M = Qnorm + mu*I ; Qnorm_ii = -d_i/mue
    Msh[tid] = qv * inv + ((i == j) ? (mu - dsh[i] * inv) : 0.0f);

    float c0 = (i == j) ? 1.0f : 0.0f;   // C_0 = I
    Ca[tid] = c0;
    g_C[(mk * NT + 0) * S * S + tid] = c0;
    __syncthreads();

    float* cur = Ca;
    float* nxt = Cb;
    for (int n = 1; n < NT; n++) {
        float acc = 0.0f;
#pragma unroll
        for (int t = 0; t < S; t++) acc += cur[i * S + t] * Msh[t * S + j];
        acc *= (1.0f / (float)n);
        nxt[tid] = acc;
        g_C[(mk * NT + n) * S * S + tid] = acc;
        __syncthreads();
        float* tmp = cur; cur = nxt; nxt = tmp;
    }
}

// ---------------------------------------------------------------------------
// Kernel B: evaluate P(tau) = exp(-tau*mu) * Horner_n(tau; C_n) per (m,b,k).
// Coefficients live in registers; each thread owns 2 matrix entries.
// Grid: (m*k) * (b/16) = 128 blocks x 256 threads.
// ---------------------------------------------------------------------------
__global__ void expm_kernel(const int* __restrict__ rate_idx,
                            const float* __restrict__ tau_k) {
    const int bx    = blockIdx.x;        // 0..127
    const int chunk = bx & 31;           // 32 chunks of 16 b's
    const int mk    = bx >> 5;           // 0..3
    const int mm    = mk >> 1, kk = mk & 1;
    const int tid   = threadIdx.x;       // 0..255

    const int e0 = tid;
    const int e1 = tid + 256;
    const bool has1 = (e1 < S * S);

    const float* C = g_C + mk * NT * S * S;
    float c0[NT], c1[NT];
#pragma unroll
    for (int n = 0; n < NT; n++) c0[n] = C[n * S * S + e0];
#pragma unroll
    for (int n = 0; n < NT; n++) c1[n] = has1 ? C[n * S * S + e1] : 0.0f;

    const float mu = g_mu[mk];
    float* P = reinterpret_cast<float*>(g_P4);

    for (int bb = 0; bb < 16; bb++) {
        const int b = chunk * 16 + bb;
        const int ridx = rate_idx[mm * NB + b];
        const float tau = softplusf(tau_k[mm * NRATES + ridx]);
        const float sc = expf(-tau * mu);

        float a0 = c0[NT - 1], a1 = c1[NT - 1];
#pragma unroll
        for (int n = NT - 2; n >= 0; n--) {
            a0 = fmaf(a0, tau, c0[n]);
            a1 = fmaf(a1, tau, c1[n]);
        }
        const int base = ((mm * NB + b) * KK + kk) * S * S;
        P[base + e0] = a0 * sc;
        if (has1) P[base + e1] = a1 * sc;
    }
}

// ---------------------------------------------------------------------------
// Kernel C: gather out[m,b,l,k,:] = P[m,b,k, seq[m,b,l], :].
// One block per (m,b); P slice (3.2 KB) + seq (2 KB) cached in SMEM;
// 80 KB contiguous float4 stores per block (fully coalesced). DRAM-bound.
// Grid: 1024 blocks x 256 threads.
// ---------------------------------------------------------------------------
__global__ void gather_kernel(const int* __restrict__ seq,
                              float4* __restrict__ out4) {
    __shared__ float4 Psh[KK * S * 5];   // 200 float4 = (k,row,s4)
    __shared__ int seqsh[LL];

    const int mb  = blockIdx.x;          // 0..1023  (m*512 + b)
    const int tid = threadIdx.x;         // 0..255

    const float4* Pg = g_P4 + mb * 200;
    if (tid < 200) Psh[tid] = Pg[tid];

    const int* sq = seq + mb * LL;
    seqsh[tid]       = sq[tid];
    seqsh[tid + 256] = sq[tid + 256];
    __syncthreads();

    float4* ob = out4 + (size_t)mb * 5120;   // 512*2*5 float4 per (m,b)
#pragma unroll
    for (int it = 0; it < 20; it++) {
        const int idx = it * 256 + tid;
        const int l  = idx / 10;             // const-div -> mul/shift
        const int r  = idx - l * 10;
        const int kk = r / 5;
        const int s4 = r - kk * 5;
        const int row = seqsh[l];
        ob[idx] = Psh[kk * 100 + row * 5 + s4];
    }
}

// ---------------------------------------------------------------------------
extern "C" void kernel_launch(void* const* d_in, const int* in_sizes, int n_in,
                              void* d_out, int out_size) {
    const int*   seq  = (const int*)d_in[0];    // sequences (m,b,L) int32
    const int*   ridx = (const int*)d_in[1];    // rate_indices (m,b) int32
    const float* tauk = (const float*)d_in[2];  // tau_kernel (m,num_rates) f32
    const float* exch = (const float*)d_in[3];  // exchangeability (m,k,S,S) f32
    const float* equi = (const float*)d_in[4];  // equilibrium (m,k,S) f32

    setup_kernel<<<MM * KK, S * S>>>(exch, equi);
    expm_kernel<<<MM * KK * (NB / 16), 256>>>(ridx, tauk);
    gather_kernel<<<MM * NB, 256>>>(seq, (float4*)d_out);
}